// round 5
// baseline (speedup 1.0000x reference)
#include <cuda_runtime.h>
#include <cuda_bf16.h>
#include <math.h>
#include <cstdint>

#define Lc   8
#define Bc   4
#define Sc   2048
#define Dc   256
#define SDc  512
#define Mc   (Bc*Sc)      // 8192

#define K1   1536         // 3 * 512 (xn hi/hi/lo split)
#define N1   1536         // 1024 (Bx interleaved) + 512 (gate)
#define K2   4608         // 3*1024 (hall split) + 3*512 (xn split)
#define N2   512          // interleaved y pairs
#define NCH  32
#define CHLEN 64

// ----------------------------- device scratch --------------------------------
__device__ __nv_bfloat16 g_A1[(size_t)Mc*K1];
__device__ __nv_bfloat16 g_A2[(size_t)Mc*K2];
__device__ __nv_bfloat16 g_W1[(size_t)Lc*N1*K1];   // [l][n][k]
__device__ __nv_bfloat16 g_W2[(size_t)Lc*N2*K2];   // [l][n][k]
__device__ float g_Bx[(size_t)Mc*1024];            // interleaved (bxr,bxi)
__device__ float g_gt[(size_t)Mc*512];
__device__ float g_h [(size_t)Mc*512];             // interleaved activation
__device__ float g_carry[(size_t)NCH*Bc*SDc*4];
__device__ float g_hst  [(size_t)NCH*Bc*SDc*2];

// ----------------------------- helpers ----------------------------------------
__device__ __forceinline__ uint32_t s2u(const void* p){
    uint32_t a;
    asm("{ .reg .u64 t; cvta.to.shared.u64 t, %1; cvt.u32.u64 %0, t; }" : "=r"(a) : "l"(p));
    return a;
}
__device__ __forceinline__ void cpa16(uint32_t s, const void* g){
    asm volatile("cp.async.cg.shared.global [%0], [%1], 16;" :: "r"(s), "l"(g));
}
__device__ __forceinline__ uint32_t swz(uint32_t o){ return o ^ ((o >> 3) & 0x70); }

__device__ __forceinline__ void ldsm4(uint32_t* r, uint32_t addr){
    asm volatile("ldmatrix.sync.aligned.m8n8.x4.shared.b16 {%0,%1,%2,%3}, [%4];"
        : "=r"(r[0]), "=r"(r[1]), "=r"(r[2]), "=r"(r[3]) : "r"(addr));
}
__device__ __forceinline__ void mma16816(float* d, const uint32_t* a, const uint32_t* b){
    asm volatile("mma.sync.aligned.m16n8k16.row.col.f32.bf16.bf16.f32 "
        "{%0,%1,%2,%3}, {%4,%5,%6,%7}, {%8,%9}, {%0,%1,%2,%3};"
        : "+f"(d[0]), "+f"(d[1]), "+f"(d[2]), "+f"(d[3])
        : "r"(a[0]), "r"(a[1]), "r"(a[2]), "r"(a[3]), "r"(b[0]), "r"(b[1]));
}

// ----------------------------- weight prep ------------------------------------
__global__ void prep_w1(const float* __restrict__ BWr, const float* __restrict__ BWi,
                        const float* __restrict__ gW)
{
    size_t i = (size_t)blockIdx.x * blockDim.x + threadIdx.x;
    if (i >= (size_t)Lc*N1*K1) return;
    int k = (int)(i % K1); size_t r = i / K1; int n = (int)(r % N1); int l = (int)(r / N1);
    int blk = k / 512, kk = k % 512;
    float v;
    if (n < 1024) {
        int j = n >> 1, p = n & 1;
        if (kk < 256) v = p ? BWi[((size_t)l*256+kk)*512+j] : BWr[((size_t)l*256+kk)*512+j];
        else { int kr = kk-256; v = p ? BWr[((size_t)l*256+kr)*512+j] : -BWi[((size_t)l*256+kr)*512+j]; }
    } else {
        v = gW[((size_t)l*512+kk)*512 + (n-1024)];
    }
    __nv_bfloat16 hi = __float2bfloat16(v);
    g_W1[i] = (blk == 1) ? __float2bfloat16(v - __bfloat162float(hi)) : hi;
}

__global__ void prep_w2(const float* __restrict__ CWr, const float* __restrict__ CWi,
                        const float* __restrict__ DWr, const float* __restrict__ DWi)
{
    size_t i = (size_t)blockIdx.x * blockDim.x + threadIdx.x;
    if (i >= (size_t)Lc*N2*K2) return;
    int k = (int)(i % K2); size_t r = i / K2; int n = (int)(r % N2); int l = (int)(r / N2);
    int j = n >> 1, p = n & 1;
    float v; int blk;
    if (k < 3072) {
        blk = k / 1024; int kk = k % 1024;
        if (kk < 512) v = p ? CWi[((size_t)l*512+kk)*256+j] : CWr[((size_t)l*512+kk)*256+j];
        else { int ki = kk-512; v = p ? CWr[((size_t)l*512+ki)*256+j] : -CWi[((size_t)l*512+ki)*256+j]; }
    } else {
        int k2 = k - 3072; blk = k2 / 512; int kk = k2 % 512;
        if (kk < 256) v = p ? DWi[((size_t)l*256+kk)*256+j] : DWr[((size_t)l*256+kk)*256+j];
        else { int kr = kk-256; v = p ? DWr[((size_t)l*256+kr)*256+j] : -DWi[((size_t)l*256+kr)*256+j]; }
    }
    __nv_bfloat16 hi = __float2bfloat16(v);
    g_W2[i] = (blk == 1) ? __float2bfloat16(v - __bfloat162float(hi)) : hi;
}

// ----------------------------- LayerNorm ---------------------------------------
__global__ void ln_kernel(const float* __restrict__ src,
                          const float* __restrict__ gw, const float* __restrict__ bw,
                          int final_mode, float* __restrict__ outInter)
{
    int m = blockIdx.x;
    int d = threadIdx.x;
    const float* row = src + (size_t)m * Dc * 2;
    float hr = row[2*d], hi = row[2*d+1];

    float v0 = hr, v1 = hi, v2 = hr*hr, v3 = hi*hi;
    #pragma unroll
    for (int o = 16; o > 0; o >>= 1) {
        v0 += __shfl_down_sync(0xffffffffu, v0, o);
        v1 += __shfl_down_sync(0xffffffffu, v1, o);
        v2 += __shfl_down_sync(0xffffffffu, v2, o);
        v3 += __shfl_down_sync(0xffffffffu, v3, o);
    }
    __shared__ float sm[4][8];
    __shared__ float stats[4];
    int w = d >> 5, ln = d & 31;
    if (ln == 0) { sm[0][w]=v0; sm[1][w]=v1; sm[2][w]=v2; sm[3][w]=v3; }
    __syncthreads();
    if (d == 0) {
        float s0=0,s1=0,s2=0,s3=0;
        #pragma unroll
        for (int i=0;i<8;i++){ s0+=sm[0][i]; s1+=sm[1][i]; s2+=sm[2][i]; s3+=sm[3][i]; }
        float inv = 1.0f / (float)Dc;
        float mur = s0*inv, mui = s1*inv;
        stats[0]=mur; stats[1]=rsqrtf(s2*inv - mur*mur + 1e-5f);
        stats[2]=mui; stats[3]=rsqrtf(s3*inv - mui*mui + 1e-5f);
    }
    __syncthreads();
    float nr = (hr - stats[0]) * stats[1] * gw[d] + bw[d];
    float ni = (hi - stats[2]) * stats[3] * gw[d] + bw[d];

    if (final_mode) {
        float* o = outInter + (size_t)m*Dc*2;
        o[2*d] = nr; o[2*d+1] = ni;
    } else {
        __nv_bfloat16 rh = __float2bfloat16(nr);
        __nv_bfloat16 rl = __float2bfloat16(nr - __bfloat162float(rh));
        __nv_bfloat16 ih = __float2bfloat16(ni);
        __nv_bfloat16 il = __float2bfloat16(ni - __bfloat162float(ih));
        __nv_bfloat16* a1 = g_A1 + (size_t)m*K1;
        a1[d]=rh; a1[256+d]=ih; a1[512+d]=rh; a1[768+d]=ih; a1[1024+d]=rl; a1[1280+d]=il;
        __nv_bfloat16* a2 = g_A2 + (size_t)m*K2 + 3072;
        a2[d]=rh; a2[256+d]=ih; a2[512+d]=rh; a2[768+d]=ih; a2[1024+d]=rl; a2[1280+d]=il;
    }
}

// ----------------------------- scan (chunked) ----------------------------------
__global__ void scan1(int layer, const float* __restrict__ theta, const float* __restrict__ damp)
{
    int t = blockIdx.x*blockDim.x + threadIdx.x;   // 65536
    int sd = t & 511, ch = (t >> 9) & 31, b = t >> 14;
    float th = theta[layer*SDc+sd], dp = damp[layer*SDc+sd];
    float dm = 0.5f + 0.5f/(1.f+expf(-dp));
    float cd = cosf(th)*dm, sn = sinf(th)*dm;
    float Ar=1.f, Ai=0.f, Br=0.f, Bi=0.f;
    int base_row = b*Sc + ch*CHLEN;
    for (int s=0;s<CHLEN;s++){
        int row = base_row + s;
        float g = g_gt[(size_t)row*512+sd];
        float2 bx = *(const float2*)&g_Bx[(size_t)row*1024 + 2*sd];
        float og = 1.f - g;
        float ar = og*cd, ai = og*sn;
        float nAr = ar*Ar - ai*Ai, nAi = ar*Ai + ai*Ar;
        float nBr = ar*Br - ai*Bi + g*bx.x;
        float nBi = ar*Bi + ai*Br + g*bx.y;
        Ar=nAr; Ai=nAi; Br=nBr; Bi=nBi;
    }
    size_t o = ((size_t)ch*Bc*SDc + (size_t)b*SDc + sd)*4;
    float4 cc; cc.x=Ar; cc.y=Ai; cc.z=Br; cc.w=Bi;
    *(float4*)&g_carry[o] = cc;
}

__global__ void scan2(int layer, const float* __restrict__ h0, float* __restrict__ hfin)
{
    int t = blockIdx.x*blockDim.x + threadIdx.x;
    if (t >= Bc*SDc) return;
    int b = t / SDc, sd = t % SDc;
    size_t hidx = ((size_t)(layer*Bc+b)*SDc + sd)*2;
    float hr = h0[hidx], hi = h0[hidx+1];
    for (int ch = 0; ch < NCH; ch++){
        size_t o = (size_t)ch*Bc*SDc + t;
        g_hst[o*2] = hr; g_hst[o*2+1] = hi;
        float4 cc = *(const float4*)&g_carry[o*4];
        float nr = cc.x*hr - cc.y*hi + cc.z;
        float ni = cc.x*hi + cc.y*hr + cc.w;
        hr = nr; hi = ni;
    }
    hfin[hidx] = hr; hfin[hidx+1] = hi;
}

__global__ void scan3(int layer, const float* __restrict__ theta, const float* __restrict__ damp)
{
    int t = blockIdx.x*blockDim.x + threadIdx.x;
    int sd = t & 511, ch = (t >> 9) & 31, b = t >> 14;
    float th = theta[layer*SDc+sd], dp = damp[layer*SDc+sd];
    float dm = 0.5f + 0.5f/(1.f+expf(-dp));
    float cd = cosf(th)*dm, sn = sinf(th)*dm;
    size_t o = (size_t)ch*Bc*SDc + (size_t)b*SDc + sd;
    float hr = g_hst[o*2], hi = g_hst[o*2+1];
    int base_row = b*Sc + ch*CHLEN;
    for (int s=0;s<CHLEN;s++){
        int row = base_row + s;
        float g = g_gt[(size_t)row*512+sd];
        float2 bx = *(const float2*)&g_Bx[(size_t)row*1024 + 2*sd];
        float tr = hr*cd - hi*sn, ti = hr*sn + hi*cd;
        float og = 1.f - g;
        hr = fmaf(g, bx.x, og*tr);
        hi = fmaf(g, bx.y, og*ti);
        __nv_bfloat16 hh = __float2bfloat16(hr);
        __nv_bfloat16 hl = __float2bfloat16(hr - __bfloat162float(hh));
        __nv_bfloat16 ih = __float2bfloat16(hi);
        __nv_bfloat16 il = __float2bfloat16(hi - __bfloat162float(ih));
        __nv_bfloat16* a2 = g_A2 + (size_t)row*K2;
        a2[sd]=hh; a2[512+sd]=ih; a2[1024+sd]=hh; a2[1536+sd]=ih; a2[2048+sd]=hl; a2[2560+sd]=il;
    }
}

// ----------------------------- HMMA GEMM ---------------------------------------
// D[m][n] = sum_k A[m][k] * W[n][k]; 128x128 CTA tile, 512 threads (4x4 warps,
// each 32x32), BK=64, 3-stage cp.async pipeline.
// mode 0: n<1024 -> oBx; n>=1024 -> oGt = sigmoid(v + gb)
// mode 1: pairs (2j,2j+1)=(yr,yi): hOut = resid + 0.1*(yr*y + y)
#define ST 3
#define STAGE_BYTES 32768          // A 16KB + B 16KB
#define GEMM_SMEM (ST*STAGE_BYTES) // 96KB

__global__ void __launch_bounds__(512, 1)
mma_gemm(const __nv_bfloat16* __restrict__ A, const __nv_bfloat16* __restrict__ W,
         int K, int mode,
         float* __restrict__ oBx, float* __restrict__ oGt, const float* __restrict__ gb,
         const float* __restrict__ resid, float* __restrict__ hOut)
{
    extern __shared__ char smem[];
    uint32_t sb = s2u(smem);
    int tid = threadIdx.x, wid = tid >> 5, L = tid & 31;
    int m0 = blockIdx.y * 128, n0 = blockIdx.x * 128;
    const int NK = K >> 6;

    // ---- cp.async mapping: 4 x 16B chunks per thread per stage ----
    const __nv_bfloat16* gbaseA = A + (size_t)m0 * K;
    const __nv_bfloat16* gbaseB = W + (size_t)n0 * K;
    uint32_t soff[4]; uint32_t goff[4]; uint32_t isB[4];
    #pragma unroll
    for (int i = 0; i < 4; i++) {
        int q = tid + i*512;          // 0..2047
        isB[i] = (uint32_t)(q >> 10);
        int qq = q & 1023;
        int r = qq >> 3, c = qq & 7;
        goff[i] = (uint32_t)(r * K + c * 8);
        soff[i] = (isB[i] ? 16384u : 0u) + swz((uint32_t)(r*128 + c*16));
    }

    // ---- ldmatrix lane addressing (warp = 32x32 tile) ----
    int wm = wid >> 2, wn = wid & 3;
    int rowA0 = wm*32 + (L & 7) + ((L >> 3) & 1) * 8;
    uint32_t aBase = (uint32_t)rowA0 * 128; uint32_t aS = (uint32_t)(rowA0 & 7);
    uint32_t aC = (uint32_t)(L >> 4);
    int rowB0 = wn*32 + (L & 7) + ((L >> 4) & 1) * 8;
    uint32_t bBase = 16384u + (uint32_t)rowB0 * 128; uint32_t bS = (uint32_t)(rowB0 & 7);
    uint32_t bC = (uint32_t)((L >> 3) & 1);

    float c[2][4][4];
    #pragma unroll
    for (int i=0;i<2;i++)
        #pragma unroll
        for (int j=0;j<4;j++)
            #pragma unroll
            for (int e=0;e<4;e++) c[i][j][e] = 0.f;

    // ---- prologue: load stages 0..ST-2 ----
    #pragma unroll
    for (int s = 0; s < ST-1; s++) {
        if (s < NK) {
            uint32_t st = sb + s*STAGE_BYTES;
            uint32_t kb = (uint32_t)(s * 64);
            #pragma unroll
            for (int i = 0; i < 4; i++) {
                const __nv_bfloat16* g = (isB[i] ? gbaseB : gbaseA) + goff[i] + kb;
                cpa16(st + soff[i], g);
            }
        }
        asm volatile("cp.async.commit_group;" ::: "memory");
    }

    for (int ki = 0; ki < NK; ki++) {
        asm volatile("cp.async.wait_group %0;" :: "n"(ST-2) : "memory");
        __syncthreads();

        // issue loads for stage ki+ST-1 first (overlap DMA with compute)
        int ls = ki + ST - 1;
        if (ls < NK) {
            uint32_t st2 = sb + (uint32_t)(ls % ST) * STAGE_BYTES;
            uint32_t kb = (uint32_t)(ls * 64);
            #pragma unroll
            for (int i = 0; i < 4; i++) {
                const __nv_bfloat16* g = (isB[i] ? gbaseB : gbaseA) + goff[i] + kb;
                cpa16(st2 + soff[i], g);
            }
        }
        asm volatile("cp.async.commit_group;" ::: "memory");

        uint32_t st = sb + (uint32_t)(ki % ST) * STAGE_BYTES;
        #pragma unroll
        for (int kk = 0; kk < 4; kk++) {
            uint32_t a[2][4], b[2][4];
            uint32_t ca = (uint32_t)(kk*2);
            #pragma unroll
            for (int mt = 0; mt < 2; mt++)
                ldsm4(a[mt], st + aBase + (uint32_t)mt*2048 + (((ca + aC) ^ aS) << 4));
            #pragma unroll
            for (int bt = 0; bt < 2; bt++)
                ldsm4(b[bt], st + bBase + (uint32_t)bt*2048 + (((ca + bC) ^ bS) << 4));
            #pragma unroll
            for (int mt = 0; mt < 2; mt++)
                #pragma unroll
                for (int nt = 0; nt < 4; nt++)
                    mma16816(c[mt][nt], a[mt], &b[nt>>1][(nt&1)*2]);
        }
    }

    // ---- epilogue: direct float2 stores ----
    int lrow = L >> 2, lcol = (L & 3) * 2;
    int mRow = m0 + wm*32 + lrow;
    int nCol = n0 + wn*32 + lcol;
    #pragma unroll
    for (int mt = 0; mt < 2; mt++) {
        #pragma unroll
        for (int nt = 0; nt < 4; nt++) {
            int row = mRow + mt*16;
            int col = nCol + nt*8;
            float* cc = c[mt][nt];
            if (mode == 0) {
                if (col < 1024) {
                    float2 v0; v0.x = cc[0]; v0.y = cc[1];
                    float2 v1; v1.x = cc[2]; v1.y = cc[3];
                    *(float2*)&oBx[(size_t)row*1024 + col] = v0;
                    *(float2*)&oBx[(size_t)(row+8)*1024 + col] = v1;
                } else {
                    int gc = col - 1024;
                    float b0 = gb[gc], b1 = gb[gc+1];
                    float2 v0, v1;
                    v0.x = 1.f/(1.f+expf(-(cc[0]+b0)));
                    v0.y = 1.f/(1.f+expf(-(cc[1]+b1)));
                    v1.x = 1.f/(1.f+expf(-(cc[2]+b0)));
                    v1.y = 1.f/(1.f+expf(-(cc[3]+b1)));
                    *(float2*)&oGt[(size_t)row*512 + gc] = v0;
                    *(float2*)&oGt[(size_t)(row+8)*512 + gc] = v1;
                }
            } else {
                float2 r0 = *(const float2*)&resid[(size_t)row*512 + col];
                float2 r1 = *(const float2*)&resid[(size_t)(row+8)*512 + col];
                float2 v0, v1;
                v0.x = r0.x + 0.1f*(cc[0]*cc[0] + cc[0]);
                v0.y = r0.y + 0.1f*(cc[0]*cc[1] + cc[1]);
                v1.x = r1.x + 0.1f*(cc[2]*cc[2] + cc[2]);
                v1.y = r1.y + 0.1f*(cc[2]*cc[3] + cc[3]);
                *(float2*)&hOut[(size_t)row*512 + col] = v0;
                *(float2*)&hOut[(size_t)(row+8)*512 + col] = v1;
            }
        }
    }
}

// ----------------------------- host ---------------------------------------------
extern "C" void kernel_launch(void* const* d_in, const int* in_sizes, int n_in,
                              void* d_out, int out_size)
{
    const float* x      = (const float*)d_in[0];
    const float* h0     = (const float*)d_in[1];
    const float* theta  = (const float*)d_in[2];
    const float* damp_p = (const float*)d_in[3];
    const float* BWr    = (const float*)d_in[4];
    const float* BWi    = (const float*)d_in[5];
    const float* CWr    = (const float*)d_in[6];
    const float* CWi    = (const float*)d_in[7];
    const float* DWr    = (const float*)d_in[8];
    const float* DWi    = (const float*)d_in[9];
    const float* gW     = (const float*)d_in[10];
    const float* gb     = (const float*)d_in[11];
    const float* ng     = (const float*)d_in[12];
    const float* nb     = (const float*)d_in[13];
    const float* og     = (const float*)d_in[14];
    const float* ob     = (const float*)d_in[15];
    float* out = (float*)d_out;

    cudaFuncSetAttribute(mma_gemm, cudaFuncAttributeMaxDynamicSharedMemorySize, GEMM_SMEM);

    __nv_bfloat16 *a1, *a2, *w1, *w2;
    float *bx, *gt, *hbuf;
    cudaGetSymbolAddress((void**)&a1, g_A1);
    cudaGetSymbolAddress((void**)&a2, g_A2);
    cudaGetSymbolAddress((void**)&w1, g_W1);
    cudaGetSymbolAddress((void**)&w2, g_W2);
    cudaGetSymbolAddress((void**)&bx, g_Bx);
    cudaGetSymbolAddress((void**)&gt, g_gt);
    cudaGetSymbolAddress((void**)&hbuf, g_h);

    float* hfin = out + (size_t)Mc*Dc*2;

    {
        size_t n1 = (size_t)Lc*N1*K1;
        prep_w1<<<(unsigned)((n1+255)/256), 256>>>(BWr, BWi, gW);
        size_t n2 = (size_t)Lc*N2*K2;
        prep_w2<<<(unsigned)((n2+255)/256), 256>>>(CWr, CWi, DWr, DWi);
    }

    for (int l = 0; l < Lc; l++) {
        const float* src = (l == 0) ? x : hbuf;

        ln_kernel<<<Mc, 256>>>(src, ng + l*Dc, nb + l*Dc, 0, nullptr);

        // GEMM1: Bx + gates
        {
            dim3 g(N1/128, Mc/128);
            mma_gemm<<<g, 512, GEMM_SMEM>>>(a1, w1 + (size_t)l*N1*K1, K1, 0,
                                            bx, gt, gb + (size_t)l*SDc, nullptr, nullptr);
        }

        scan1<<<256, 256>>>(l, theta, damp_p);
        scan2<<<8, 256>>>(l, h0, hfin);
        scan3<<<256, 256>>>(l, theta, damp_p);

        // GEMM2: y = C*hall + D*xn; nonlinearity + residual fused
        {
            dim3 g(N2/128, Mc/128);
            mma_gemm<<<g, 512, GEMM_SMEM>>>(a2, w2 + (size_t)l*N2*K2, K2, 1,
                                            nullptr, nullptr, nullptr, src, hbuf);
        }
    }

    ln_kernel<<<Mc, 256>>>(hbuf, og, ob, 1, out);
}

// round 6
// speedup vs baseline: 1.1809x; 1.1809x over previous
#include <cuda_runtime.h>
#include <cuda_bf16.h>
#include <math.h>
#include <cstdint>

#define Lc   8
#define Bc   4
#define Sc   2048
#define Dc   256
#define SDc  512
#define Mc   (Bc*Sc)      // 8192

#define K1   1536         // 3 * 512 (xn hi/hi/lo split)
#define N1   1536         // 1024 (Bx interleaved) + 512 (gate)
#define K2   4608         // 3*1024 (hall split) + 3*512 (xn split)
#define N2   512          // interleaved y pairs
#define NCH  32
#define CHLEN 64

// ----------------------------- device scratch --------------------------------
__device__ __nv_bfloat16 g_A1[(size_t)Mc*K1];
__device__ __nv_bfloat16 g_A2[(size_t)Mc*K2];
__device__ __nv_bfloat16 g_W1[(size_t)Lc*N1*K1];   // [l][n][k]
__device__ __nv_bfloat16 g_W2[(size_t)Lc*N2*K2];   // [l][n][k]
__device__ float g_Bx[(size_t)Mc*1024];            // interleaved (bxr,bxi)
__device__ float g_gt[(size_t)Mc*512];
__device__ float g_h [(size_t)Mc*512];             // interleaved activation
__device__ float g_carry[(size_t)NCH*Bc*SDc*4];
__device__ float g_hst  [(size_t)NCH*Bc*SDc*2];

// ----------------------------- helpers ----------------------------------------
__device__ __forceinline__ uint32_t s2u(const void* p){
    uint32_t a;
    asm("{ .reg .u64 t; cvta.to.shared.u64 t, %1; cvt.u32.u64 %0, t; }" : "=r"(a) : "l"(p));
    return a;
}
__device__ __forceinline__ void cpa16(uint32_t s, const void* g){
    asm volatile("cp.async.cg.shared.global [%0], [%1], 16;" :: "r"(s), "l"(g));
}
__device__ __forceinline__ uint32_t swz(uint32_t o){ return o ^ ((o >> 3) & 0x70); }

__device__ __forceinline__ void ldsm4(uint32_t* r, uint32_t addr){
    asm volatile("ldmatrix.sync.aligned.m8n8.x4.shared.b16 {%0,%1,%2,%3}, [%4];"
        : "=r"(r[0]), "=r"(r[1]), "=r"(r[2]), "=r"(r[3]) : "r"(addr));
}
__device__ __forceinline__ void mma16816(float* d, const uint32_t* a, const uint32_t* b){
    asm volatile("mma.sync.aligned.m16n8k16.row.col.f32.bf16.bf16.f32 "
        "{%0,%1,%2,%3}, {%4,%5,%6,%7}, {%8,%9}, {%0,%1,%2,%3};"
        : "+f"(d[0]), "+f"(d[1]), "+f"(d[2]), "+f"(d[3])
        : "r"(a[0]), "r"(a[1]), "r"(a[2]), "r"(a[3]), "r"(b[0]), "r"(b[1]));
}

// ----------------------------- weight prep ------------------------------------
__global__ void prep_w1(const float* __restrict__ BWr, const float* __restrict__ BWi,
                        const float* __restrict__ gW)
{
    size_t i = (size_t)blockIdx.x * blockDim.x + threadIdx.x;
    if (i >= (size_t)Lc*N1*K1) return;
    int k = (int)(i % K1); size_t r = i / K1; int n = (int)(r % N1); int l = (int)(r / N1);
    int blk = k / 512, kk = k % 512;
    float v;
    if (n < 1024) {
        int j = n >> 1, p = n & 1;
        if (kk < 256) v = p ? BWi[((size_t)l*256+kk)*512+j] : BWr[((size_t)l*256+kk)*512+j];
        else { int kr = kk-256; v = p ? BWr[((size_t)l*256+kr)*512+j] : -BWi[((size_t)l*256+kr)*512+j]; }
    } else {
        v = gW[((size_t)l*512+kk)*512 + (n-1024)];
    }
    __nv_bfloat16 hi = __float2bfloat16(v);
    g_W1[i] = (blk == 1) ? __float2bfloat16(v - __bfloat162float(hi)) : hi;
}

__global__ void prep_w2(const float* __restrict__ CWr, const float* __restrict__ CWi,
                        const float* __restrict__ DWr, const float* __restrict__ DWi)
{
    size_t i = (size_t)blockIdx.x * blockDim.x + threadIdx.x;
    if (i >= (size_t)Lc*N2*K2) return;
    int k = (int)(i % K2); size_t r = i / K2; int n = (int)(r % N2); int l = (int)(r / N2);
    int j = n >> 1, p = n & 1;
    float v; int blk;
    if (k < 3072) {
        blk = k / 1024; int kk = k % 1024;
        if (kk < 512) v = p ? CWi[((size_t)l*512+kk)*256+j] : CWr[((size_t)l*512+kk)*256+j];
        else { int ki = kk-512; v = p ? CWr[((size_t)l*512+ki)*256+j] : -CWi[((size_t)l*512+ki)*256+j]; }
    } else {
        int k2 = k - 3072; blk = k2 / 512; int kk = k2 % 512;
        if (kk < 256) v = p ? DWi[((size_t)l*256+kk)*256+j] : DWr[((size_t)l*256+kk)*256+j];
        else { int kr = kk-256; v = p ? DWr[((size_t)l*256+kr)*256+j] : -DWi[((size_t)l*256+kr)*256+j]; }
    }
    __nv_bfloat16 hi = __float2bfloat16(v);
    g_W2[i] = (blk == 1) ? __float2bfloat16(v - __bfloat162float(hi)) : hi;
}

// ----------------------------- LayerNorm ---------------------------------------
__global__ void ln_kernel(const float* __restrict__ src,
                          const float* __restrict__ gw, const float* __restrict__ bw,
                          int final_mode, float* __restrict__ outInter)
{
    int m = blockIdx.x;
    int d = threadIdx.x;
    const float* row = src + (size_t)m * Dc * 2;
    float hr = row[2*d], hi = row[2*d+1];

    float v0 = hr, v1 = hi, v2 = hr*hr, v3 = hi*hi;
    #pragma unroll
    for (int o = 16; o > 0; o >>= 1) {
        v0 += __shfl_down_sync(0xffffffffu, v0, o);
        v1 += __shfl_down_sync(0xffffffffu, v1, o);
        v2 += __shfl_down_sync(0xffffffffu, v2, o);
        v3 += __shfl_down_sync(0xffffffffu, v3, o);
    }
    __shared__ float sm[4][8];
    __shared__ float stats[4];
    int w = d >> 5, ln = d & 31;
    if (ln == 0) { sm[0][w]=v0; sm[1][w]=v1; sm[2][w]=v2; sm[3][w]=v3; }
    __syncthreads();
    if (d == 0) {
        float s0=0,s1=0,s2=0,s3=0;
        #pragma unroll
        for (int i=0;i<8;i++){ s0+=sm[0][i]; s1+=sm[1][i]; s2+=sm[2][i]; s3+=sm[3][i]; }
        float inv = 1.0f / (float)Dc;
        float mur = s0*inv, mui = s1*inv;
        stats[0]=mur; stats[1]=rsqrtf(s2*inv - mur*mur + 1e-5f);
        stats[2]=mui; stats[3]=rsqrtf(s3*inv - mui*mui + 1e-5f);
    }
    __syncthreads();
    float nr = (hr - stats[0]) * stats[1] * gw[d] + bw[d];
    float ni = (hi - stats[2]) * stats[3] * gw[d] + bw[d];

    if (final_mode) {
        float* o = outInter + (size_t)m*Dc*2;
        o[2*d] = nr; o[2*d+1] = ni;
    } else {
        __nv_bfloat16 rh = __float2bfloat16(nr);
        __nv_bfloat16 rl = __float2bfloat16(nr - __bfloat162float(rh));
        __nv_bfloat16 ih = __float2bfloat16(ni);
        __nv_bfloat16 il = __float2bfloat16(ni - __bfloat162float(ih));
        __nv_bfloat16* a1 = g_A1 + (size_t)m*K1;
        a1[d]=rh; a1[256+d]=ih; a1[512+d]=rh; a1[768+d]=ih; a1[1024+d]=rl; a1[1280+d]=il;
        __nv_bfloat16* a2 = g_A2 + (size_t)m*K2 + 3072;
        a2[d]=rh; a2[256+d]=ih; a2[512+d]=rh; a2[768+d]=ih; a2[1024+d]=rl; a2[1280+d]=il;
    }
}

// ----------------------------- scan (chunked) ----------------------------------
__global__ void scan1(int layer, const float* __restrict__ theta, const float* __restrict__ damp)
{
    int t = blockIdx.x*blockDim.x + threadIdx.x;   // 65536
    int sd = t & 511, ch = (t >> 9) & 31, b = t >> 14;
    float th = theta[layer*SDc+sd], dp = damp[layer*SDc+sd];
    float dm = 0.5f + 0.5f/(1.f+expf(-dp));
    float cd = cosf(th)*dm, sn = sinf(th)*dm;
    float Ar=1.f, Ai=0.f, Br=0.f, Bi=0.f;
    int base_row = b*Sc + ch*CHLEN;
    for (int s=0;s<CHLEN;s++){
        int row = base_row + s;
        float g = g_gt[(size_t)row*512+sd];
        float2 bx = *(const float2*)&g_Bx[(size_t)row*1024 + 2*sd];
        float og = 1.f - g;
        float ar = og*cd, ai = og*sn;
        float nAr = ar*Ar - ai*Ai, nAi = ar*Ai + ai*Ar;
        float nBr = ar*Br - ai*Bi + g*bx.x;
        float nBi = ar*Bi + ai*Br + g*bx.y;
        Ar=nAr; Ai=nAi; Br=nBr; Bi=nBi;
    }
    size_t o = ((size_t)ch*Bc*SDc + (size_t)b*SDc + sd)*4;
    float4 cc; cc.x=Ar; cc.y=Ai; cc.z=Br; cc.w=Bi;
    *(float4*)&g_carry[o] = cc;
}

__global__ void scan2(int layer, const float* __restrict__ h0, float* __restrict__ hfin)
{
    int t = blockIdx.x*blockDim.x + threadIdx.x;
    if (t >= Bc*SDc) return;
    int b = t / SDc, sd = t % SDc;
    size_t hidx = ((size_t)(layer*Bc+b)*SDc + sd)*2;
    float hr = h0[hidx], hi = h0[hidx+1];
    for (int ch = 0; ch < NCH; ch++){
        size_t o = (size_t)ch*Bc*SDc + t;
        g_hst[o*2] = hr; g_hst[o*2+1] = hi;
        float4 cc = *(const float4*)&g_carry[o*4];
        float nr = cc.x*hr - cc.y*hi + cc.z;
        float ni = cc.x*hi + cc.y*hr + cc.w;
        hr = nr; hi = ni;
    }
    hfin[hidx] = hr; hfin[hidx+1] = hi;
}

__global__ void scan3(int layer, const float* __restrict__ theta, const float* __restrict__ damp)
{
    int t = blockIdx.x*blockDim.x + threadIdx.x;
    int sd = t & 511, ch = (t >> 9) & 31, b = t >> 14;
    float th = theta[layer*SDc+sd], dp = damp[layer*SDc+sd];
    float dm = 0.5f + 0.5f/(1.f+expf(-dp));
    float cd = cosf(th)*dm, sn = sinf(th)*dm;
    size_t o = (size_t)ch*Bc*SDc + (size_t)b*SDc + sd;
    float hr = g_hst[o*2], hi = g_hst[o*2+1];
    int base_row = b*Sc + ch*CHLEN;
    for (int s=0;s<CHLEN;s++){
        int row = base_row + s;
        float g = g_gt[(size_t)row*512+sd];
        float2 bx = *(const float2*)&g_Bx[(size_t)row*1024 + 2*sd];
        float tr = hr*cd - hi*sn, ti = hr*sn + hi*cd;
        float og = 1.f - g;
        hr = fmaf(g, bx.x, og*tr);
        hi = fmaf(g, bx.y, og*ti);
        __nv_bfloat16 hh = __float2bfloat16(hr);
        __nv_bfloat16 hl = __float2bfloat16(hr - __bfloat162float(hh));
        __nv_bfloat16 ih = __float2bfloat16(hi);
        __nv_bfloat16 il = __float2bfloat16(hi - __bfloat162float(ih));
        __nv_bfloat16* a2 = g_A2 + (size_t)row*K2;
        a2[sd]=hh; a2[512+sd]=ih; a2[1024+sd]=hh; a2[1536+sd]=ih; a2[2048+sd]=hl; a2[2560+sd]=il;
    }
}

// ----------------------------- HMMA GEMM ---------------------------------------
// D[m][n] = sum_k A[m][k] * W[n][k]; 128x128 tile, BK=64, 3-stage cp.async,
// 256 threads (2x4 warps, 64x32 each), 2 CTAs/SM via reg cap.
// mode 0: n<1024 -> oBx; n>=1024 -> oGt = sigmoid(v + gb)
// mode 1: pairs (2j,2j+1)=(yr,yi): hOut = resid + 0.1*(yr*y + y)
#define ST 3
#define STAGE_BYTES 32768          // A 16KB + B 16KB
#define GEMM_SMEM (ST*STAGE_BYTES) // 96KB -> 2 CTAs/SM

__global__ void __launch_bounds__(256, 2)
mma_gemm(const __nv_bfloat16* __restrict__ A, const __nv_bfloat16* __restrict__ W,
         int K, int mode,
         float* __restrict__ oBx, float* __restrict__ oGt, const float* __restrict__ gb,
         const float* __restrict__ resid, float* __restrict__ hOut)
{
    extern __shared__ char smem[];
    uint32_t sb = s2u(smem);
    int tid = threadIdx.x, wid = tid >> 5, L = tid & 31;
    int m0 = blockIdx.y * 128, n0 = blockIdx.x * 128;
    const int NK = K >> 6;

    // ---- cp.async mapping: 8 x 16B chunks per thread per stage ----
    const __nv_bfloat16* gbaseA = A + (size_t)m0 * K;
    const __nv_bfloat16* gbaseB = W + (size_t)n0 * K;
    uint32_t soff[8]; uint32_t goff[8]; uint32_t isB[8];
    #pragma unroll
    for (int i = 0; i < 8; i++) {
        int q = tid + i*256;          // 0..2047
        isB[i] = (uint32_t)(q >> 10);
        int qq = q & 1023;
        int r = qq >> 3, c = qq & 7;
        goff[i] = (uint32_t)(r * K + c * 8);
        soff[i] = (isB[i] ? 16384u : 0u) + swz((uint32_t)(r*128 + c*16));
    }

    // ---- ldmatrix lane addressing (SW128) ----
    int wm = wid >> 2, wn = wid & 3;
    int rowA0 = wm*64 + (L & 7) + ((L >> 3) & 1) * 8;
    uint32_t aBase = (uint32_t)rowA0 * 128; uint32_t aS = (uint32_t)(rowA0 & 7);
    uint32_t aC = (uint32_t)(L >> 4);
    int rowB0 = wn*32 + (L & 7) + ((L >> 4) & 1) * 8;
    uint32_t bBase = 16384u + (uint32_t)rowB0 * 128; uint32_t bS = (uint32_t)(rowB0 & 7);
    uint32_t bC = (uint32_t)((L >> 3) & 1);

    float c[4][4][4];
    #pragma unroll
    for (int i=0;i<4;i++)
        #pragma unroll
        for (int j=0;j<4;j++)
            #pragma unroll
            for (int e=0;e<4;e++) c[i][j][e] = 0.f;

    // ---- prologue: load stages 0,1 ----
    #pragma unroll
    for (int s = 0; s < ST-1; s++) {
        if (s < NK) {
            uint32_t st = sb + s*STAGE_BYTES;
            uint32_t kb = (uint32_t)(s * 64);
            #pragma unroll
            for (int i = 0; i < 8; i++) {
                const __nv_bfloat16* g = (isB[i] ? gbaseB : gbaseA) + goff[i] + kb;
                cpa16(st + soff[i], g);
            }
        }
        asm volatile("cp.async.commit_group;" ::: "memory");
    }

    for (int ki = 0; ki < NK; ki++) {
        asm volatile("cp.async.wait_group %0;" :: "n"(ST-2) : "memory");
        __syncthreads();

        uint32_t st = sb + (uint32_t)(ki % ST) * STAGE_BYTES;
        #pragma unroll
        for (int kk = 0; kk < 4; kk++) {
            uint32_t a[4][4], b[2][4];
            uint32_t ca = (uint32_t)(kk*2);
            #pragma unroll
            for (int mt = 0; mt < 4; mt++)
                ldsm4(a[mt], st + aBase + (uint32_t)mt*2048 + (((ca + aC) ^ aS) << 4));
            #pragma unroll
            for (int bt = 0; bt < 2; bt++)
                ldsm4(b[bt], st + bBase + (uint32_t)bt*2048 + (((ca + bC) ^ bS) << 4));
            #pragma unroll
            for (int mt = 0; mt < 4; mt++)
                #pragma unroll
                for (int nt = 0; nt < 4; nt++)
                    mma16816(c[mt][nt], a[mt], &b[nt>>1][(nt&1)*2]);
        }

        // load stage ki+ST-1
        int ls = ki + ST - 1;
        if (ls < NK) {
            uint32_t st2 = sb + (uint32_t)(ls % ST) * STAGE_BYTES;
            uint32_t kb = (uint32_t)(ls * 64);
            #pragma unroll
            for (int i = 0; i < 8; i++) {
                const __nv_bfloat16* g = (isB[i] ? gbaseB : gbaseA) + goff[i] + kb;
                cpa16(st2 + soff[i], g);
            }
        }
        asm volatile("cp.async.commit_group;" ::: "memory");
    }

    // ---- epilogue: direct float2 stores ----
    int lrow = L >> 2, lcol = (L & 3) * 2;
    int mRow = m0 + wm*64 + lrow;
    int nCol = n0 + wn*32 + lcol;
    #pragma unroll
    for (int mt = 0; mt < 4; mt++) {
        #pragma unroll
        for (int nt = 0; nt < 4; nt++) {
            int row = mRow + mt*16;
            int col = nCol + nt*8;
            float* cc = c[mt][nt];
            if (mode == 0) {
                if (col < 1024) {
                    float2 v0; v0.x = cc[0]; v0.y = cc[1];
                    float2 v1; v1.x = cc[2]; v1.y = cc[3];
                    *(float2*)&oBx[(size_t)row*1024 + col] = v0;
                    *(float2*)&oBx[(size_t)(row+8)*1024 + col] = v1;
                } else {
                    int gc = col - 1024;
                    float b0 = gb[gc], b1 = gb[gc+1];
                    float2 v0, v1;
                    v0.x = 1.f/(1.f+expf(-(cc[0]+b0)));
                    v0.y = 1.f/(1.f+expf(-(cc[1]+b1)));
                    v1.x = 1.f/(1.f+expf(-(cc[2]+b0)));
                    v1.y = 1.f/(1.f+expf(-(cc[3]+b1)));
                    *(float2*)&oGt[(size_t)row*512 + gc] = v0;
                    *(float2*)&oGt[(size_t)(row+8)*512 + gc] = v1;
                }
            } else {
                float2 r0 = *(const float2*)&resid[(size_t)row*512 + col];
                float2 r1 = *(const float2*)&resid[(size_t)(row+8)*512 + col];
                float2 v0, v1;
                v0.x = r0.x + 0.1f*(cc[0]*cc[0] + cc[0]);
                v0.y = r0.y + 0.1f*(cc[0]*cc[1] + cc[1]);
                v1.x = r1.x + 0.1f*(cc[2]*cc[2] + cc[2]);
                v1.y = r1.y + 0.1f*(cc[2]*cc[3] + cc[3]);
                *(float2*)&hOut[(size_t)row*512 + col] = v0;
                *(float2*)&hOut[(size_t)(row+8)*512 + col] = v1;
            }
        }
    }
}

// ----------------------------- host ---------------------------------------------
extern "C" void kernel_launch(void* const* d_in, const int* in_sizes, int n_in,
                              void* d_out, int out_size)
{
    const float* x      = (const float*)d_in[0];
    const float* h0     = (const float*)d_in[1];
    const float* theta  = (const float*)d_in[2];
    const float* damp_p = (const float*)d_in[3];
    const float* BWr    = (const float*)d_in[4];
    const float* BWi    = (const float*)d_in[5];
    const float* CWr    = (const float*)d_in[6];
    const float* CWi    = (const float*)d_in[7];
    const float* DWr    = (const float*)d_in[8];
    const float* DWi    = (const float*)d_in[9];
    const float* gW     = (const float*)d_in[10];
    const float* gb     = (const float*)d_in[11];
    const float* ng     = (const float*)d_in[12];
    const float* nb     = (const float*)d_in[13];
    const float* og     = (const float*)d_in[14];
    const float* ob     = (const float*)d_in[15];
    float* out = (float*)d_out;

    cudaFuncSetAttribute(mma_gemm, cudaFuncAttributeMaxDynamicSharedMemorySize, GEMM_SMEM);

    __nv_bfloat16 *a1, *a2, *w1, *w2;
    float *bx, *gt, *hbuf;
    cudaGetSymbolAddress((void**)&a1, g_A1);
    cudaGetSymbolAddress((void**)&a2, g_A2);
    cudaGetSymbolAddress((void**)&w1, g_W1);
    cudaGetSymbolAddress((void**)&w2, g_W2);
    cudaGetSymbolAddress((void**)&bx, g_Bx);
    cudaGetSymbolAddress((void**)&gt, g_gt);
    cudaGetSymbolAddress((void**)&hbuf, g_h);

    float* hfin = out + (size_t)Mc*Dc*2;

    {
        size_t n1 = (size_t)Lc*N1*K1;
        prep_w1<<<(unsigned)((n1+255)/256), 256>>>(BWr, BWi, gW);
        size_t n2 = (size_t)Lc*N2*K2;
        prep_w2<<<(unsigned)((n2+255)/256), 256>>>(CWr, CWi, DWr, DWi);
    }

    for (int l = 0; l < Lc; l++) {
        const float* src = (l == 0) ? x : hbuf;

        ln_kernel<<<Mc, 256>>>(src, ng + l*Dc, nb + l*Dc, 0, nullptr);

        // GEMM1: Bx + gates
        {
            dim3 g(N1/128, Mc/128);
            mma_gemm<<<g, 256, GEMM_SMEM>>>(a1, w1 + (size_t)l*N1*K1, K1, 0,
                                            bx, gt, gb + (size_t)l*SDc, nullptr, nullptr);
        }

        scan1<<<256, 256>>>(l, theta, damp_p);
        scan2<<<8, 256>>>(l, h0, hfin);
        scan3<<<256, 256>>>(l, theta, damp_p);

        // GEMM2: y = C*hall + D*xn; nonlinearity + residual fused
        {
            dim3 g(N2/128, Mc/128);
            mma_gemm<<<g, 256, GEMM_SMEM>>>(a2, w2 + (size_t)l*N2*K2, K2, 1,
                                            nullptr, nullptr, nullptr, src, hbuf);
        }
    }

    ln_kernel<<<Mc, 256>>>(hbuf, og, ob, 1, out);
}

// round 7
// speedup vs baseline: 1.2590x; 1.0661x over previous
#include <cuda_runtime.h>
#include <cuda_bf16.h>
#include <math.h>
#include <cstdint>

#define Lc   8
#define Bc   4
#define Sc   2048
#define Dc   256
#define SDc  512
#define Mc   (Bc*Sc)      // 8192

#define K1   1536         // W1 k-dim: [Whi|Wlo|Whi] x 512
#define N1   1536         // 1024 (Bx interleaved) + 512 (gate)
#define K2   4608         // W2 k-dim: hall [Whi|Wlo|Whi]x1024 + xn [Whi|Wlo|Whi]x512
#define N2   512          // interleaved y pairs
#define KA1  1024         // A1 storage: [xn_hi 512 | xn_lo 512]
#define KA2  2048         // A2 storage: [hall_hi 1024 | hall_lo 1024]
#define NCH  64
#define CHLEN 32

// ----------------------------- device scratch --------------------------------
__device__ __nv_bfloat16 g_A1[(size_t)Mc*KA1];
__device__ __nv_bfloat16 g_A2[(size_t)Mc*KA2];
__device__ __nv_bfloat16 g_W1[(size_t)Lc*N1*K1];   // [l][n][k]
__device__ __nv_bfloat16 g_W2[(size_t)Lc*N2*K2];   // [l][n][k]
__device__ float g_Bx[(size_t)Mc*1024];            // interleaved (bxr,bxi)
__device__ float g_gt[(size_t)Mc*512];
__device__ float g_h [(size_t)Mc*512];             // interleaved activation
__device__ float g_carry[(size_t)NCH*Bc*SDc*4];
__device__ float g_hst  [(size_t)NCH*Bc*SDc*2];

// ----------------------------- helpers ----------------------------------------
__device__ __forceinline__ uint32_t s2u(const void* p){
    uint32_t a;
    asm("{ .reg .u64 t; cvta.to.shared.u64 t, %1; cvt.u32.u64 %0, t; }" : "=r"(a) : "l"(p));
    return a;
}
__device__ __forceinline__ void cpa16(uint32_t s, const void* g){
    asm volatile("cp.async.cg.shared.global [%0], [%1], 16;" :: "r"(s), "l"(g));
}
__device__ __forceinline__ uint32_t swz(uint32_t o){ return o ^ ((o >> 3) & 0x70); }

__device__ __forceinline__ void ldsm4(uint32_t* r, uint32_t addr){
    asm volatile("ldmatrix.sync.aligned.m8n8.x4.shared.b16 {%0,%1,%2,%3}, [%4];"
        : "=r"(r[0]), "=r"(r[1]), "=r"(r[2]), "=r"(r[3]) : "r"(addr));
}
__device__ __forceinline__ void mma16816(float* d, const uint32_t* a, const uint32_t* b){
    asm volatile("mma.sync.aligned.m16n8k16.row.col.f32.bf16.bf16.f32 "
        "{%0,%1,%2,%3}, {%4,%5,%6,%7}, {%8,%9}, {%0,%1,%2,%3};"
        : "+f"(d[0]), "+f"(d[1]), "+f"(d[2]), "+f"(d[3])
        : "r"(a[0]), "r"(a[1]), "r"(a[2]), "r"(a[3]), "r"(b[0]), "r"(b[1]));
}

// ----------------------------- weight prep (unchanged layouts) -----------------
__global__ void prep_w1(const float* __restrict__ BWr, const float* __restrict__ BWi,
                        const float* __restrict__ gW)
{
    size_t i = (size_t)blockIdx.x * blockDim.x + threadIdx.x;
    if (i >= (size_t)Lc*N1*K1) return;
    int k = (int)(i % K1); size_t r = i / K1; int n = (int)(r % N1); int l = (int)(r / N1);
    int blk = k / 512, kk = k % 512;
    float v;
    if (n < 1024) {
        int j = n >> 1, p = n & 1;
        if (kk < 256) v = p ? BWi[((size_t)l*256+kk)*512+j] : BWr[((size_t)l*256+kk)*512+j];
        else { int kr = kk-256; v = p ? BWr[((size_t)l*256+kr)*512+j] : -BWi[((size_t)l*256+kr)*512+j]; }
    } else {
        v = gW[((size_t)l*512+kk)*512 + (n-1024)];
    }
    __nv_bfloat16 hi = __float2bfloat16(v);
    g_W1[i] = (blk == 1) ? __float2bfloat16(v - __bfloat162float(hi)) : hi;
}

__global__ void prep_w2(const float* __restrict__ CWr, const float* __restrict__ CWi,
                        const float* __restrict__ DWr, const float* __restrict__ DWi)
{
    size_t i = (size_t)blockIdx.x * blockDim.x + threadIdx.x;
    if (i >= (size_t)Lc*N2*K2) return;
    int k = (int)(i % K2); size_t r = i / K2; int n = (int)(r % N2); int l = (int)(r / N2);
    int j = n >> 1, p = n & 1;
    float v; int blk;
    if (k < 3072) {
        blk = k / 1024; int kk = k % 1024;
        if (kk < 512) v = p ? CWi[((size_t)l*512+kk)*256+j] : CWr[((size_t)l*512+kk)*256+j];
        else { int ki = kk-512; v = p ? CWr[((size_t)l*512+ki)*256+j] : -CWi[((size_t)l*512+ki)*256+j]; }
    } else {
        int k2 = k - 3072; blk = k2 / 512; int kk = k2 % 512;
        if (kk < 256) v = p ? DWi[((size_t)l*256+kk)*256+j] : DWr[((size_t)l*256+kk)*256+j];
        else { int kr = kk-256; v = p ? DWr[((size_t)l*256+kr)*256+j] : -DWi[((size_t)l*256+kr)*256+j]; }
    }
    __nv_bfloat16 hi = __float2bfloat16(v);
    g_W2[i] = (blk == 1) ? __float2bfloat16(v - __bfloat162float(hi)) : hi;
}

// ----------------------------- LayerNorm (warp per row) ------------------------
__global__ void ln_kernel(const float* __restrict__ src,
                          const float* __restrict__ gw, const float* __restrict__ bw,
                          int final_mode, float* __restrict__ outInter)
{
    int warp = threadIdx.x >> 5, L = threadIdx.x & 31;
    int m = blockIdx.x * 8 + warp;
    const float4* row = (const float4*)(src + (size_t)m * 512);
    float4 v[4];
    float sr=0.f, si=0.f, qr=0.f, qi=0.f;
    #pragma unroll
    for (int j=0;j<4;j++){
        v[j] = row[L + 32*j];
        sr += v[j].x + v[j].z;  si += v[j].y + v[j].w;
        qr += v[j].x*v[j].x + v[j].z*v[j].z;
        qi += v[j].y*v[j].y + v[j].w*v[j].w;
    }
    #pragma unroll
    for (int o=16;o>0;o>>=1){
        sr += __shfl_xor_sync(0xffffffffu, sr, o);
        si += __shfl_xor_sync(0xffffffffu, si, o);
        qr += __shfl_xor_sync(0xffffffffu, qr, o);
        qi += __shfl_xor_sync(0xffffffffu, qi, o);
    }
    const float inv = 1.f/256.f;
    float mur = sr*inv, mui = si*inv;
    float isr = rsqrtf(qr*inv - mur*mur + 1e-5f);
    float isi = rsqrtf(qi*inv - mui*mui + 1e-5f);

    __nv_bfloat16* a1 = g_A1 + (size_t)m * KA1;
    float* ointer = final_mode ? (outInter + (size_t)m*512) : nullptr;

    #pragma unroll
    for (int j=0;j<4;j++){
        int f = L + 32*j;
        float2 g2 = ((const float2*)gw)[f];
        float2 b2 = ((const float2*)bw)[f];
        float nr0 = (v[j].x - mur)*isr*g2.x + b2.x;
        float ni0 = (v[j].y - mui)*isi*g2.x + b2.x;
        float nr1 = (v[j].z - mur)*isr*g2.y + b2.y;
        float ni1 = (v[j].w - mui)*isi*g2.y + b2.y;
        if (final_mode) {
            float4 o4; o4.x=nr0; o4.y=ni0; o4.z=nr1; o4.w=ni1;
            ((float4*)ointer)[f] = o4;
        } else {
            int d0 = 2*f;
            __nv_bfloat162 rh = __floats2bfloat162_rn(nr0, nr1);
            __nv_bfloat162 ih = __floats2bfloat162_rn(ni0, ni1);
            __nv_bfloat162 rl = __floats2bfloat162_rn(nr0 - __bfloat162float(rh.x),
                                                      nr1 - __bfloat162float(rh.y));
            __nv_bfloat162 il = __floats2bfloat162_rn(ni0 - __bfloat162float(ih.x),
                                                      ni1 - __bfloat162float(ih.y));
            *(__nv_bfloat162*)(a1 + d0)       = rh;
            *(__nv_bfloat162*)(a1 + 256 + d0) = ih;
            *(__nv_bfloat162*)(a1 + 512 + d0) = rl;
            *(__nv_bfloat162*)(a1 + 768 + d0) = il;
        }
    }
}

// ----------------------------- scan (chunked) ----------------------------------
__global__ void scan1(int layer, const float* __restrict__ theta, const float* __restrict__ damp)
{
    int t = blockIdx.x*blockDim.x + threadIdx.x;   // 131072
    int sd = t & 511, ch = (t >> 9) & 63, b = t >> 15;
    float th = theta[layer*SDc+sd], dp = damp[layer*SDc+sd];
    float dm = 0.5f + 0.5f/(1.f+expf(-dp));
    float cd = cosf(th)*dm, sn = sinf(th)*dm;
    float Ar=1.f, Ai=0.f, Br=0.f, Bi=0.f;
    int base_row = b*Sc + ch*CHLEN;
    for (int s=0;s<CHLEN;s++){
        int row = base_row + s;
        float g = g_gt[(size_t)row*512+sd];
        float2 bx = *(const float2*)&g_Bx[(size_t)row*1024 + 2*sd];
        float og = 1.f - g;
        float ar = og*cd, ai = og*sn;
        float nAr = ar*Ar - ai*Ai, nAi = ar*Ai + ai*Ar;
        float nBr = ar*Br - ai*Bi + g*bx.x;
        float nBi = ar*Bi + ai*Br + g*bx.y;
        Ar=nAr; Ai=nAi; Br=nBr; Bi=nBi;
    }
    size_t o = ((size_t)ch*Bc*SDc + (size_t)b*SDc + sd)*4;
    float4 cc; cc.x=Ar; cc.y=Ai; cc.z=Br; cc.w=Bi;
    *(float4*)&g_carry[o] = cc;
}

__global__ void scan2(int layer, const float* __restrict__ h0, float* __restrict__ hfin)
{
    int t = blockIdx.x*blockDim.x + threadIdx.x;
    if (t >= Bc*SDc) return;
    int b = t / SDc, sd = t % SDc;
    size_t hidx = ((size_t)(layer*Bc+b)*SDc + sd)*2;
    float hr = h0[hidx], hi = h0[hidx+1];
    for (int ch = 0; ch < NCH; ch++){
        size_t o = (size_t)ch*Bc*SDc + t;
        g_hst[o*2] = hr; g_hst[o*2+1] = hi;
        float4 cc = *(const float4*)&g_carry[o*4];
        float nr = cc.x*hr - cc.y*hi + cc.z;
        float ni = cc.x*hi + cc.y*hr + cc.w;
        hr = nr; hi = ni;
    }
    hfin[hidx] = hr; hfin[hidx+1] = hi;
}

__global__ void scan3(int layer, const float* __restrict__ theta, const float* __restrict__ damp)
{
    int t = blockIdx.x*blockDim.x + threadIdx.x;
    int sd = t & 511, ch = (t >> 9) & 63, b = t >> 15;
    float th = theta[layer*SDc+sd], dp = damp[layer*SDc+sd];
    float dm = 0.5f + 0.5f/(1.f+expf(-dp));
    float cd = cosf(th)*dm, sn = sinf(th)*dm;
    size_t o = (size_t)ch*Bc*SDc + (size_t)b*SDc + sd;
    float hr = g_hst[o*2], hi = g_hst[o*2+1];
    int base_row = b*Sc + ch*CHLEN;
    for (int s=0;s<CHLEN;s++){
        int row = base_row + s;
        float g = g_gt[(size_t)row*512+sd];
        float2 bx = *(const float2*)&g_Bx[(size_t)row*1024 + 2*sd];
        float tr = hr*cd - hi*sn, ti = hr*sn + hi*cd;
        float og = 1.f - g;
        hr = fmaf(g, bx.x, og*tr);
        hi = fmaf(g, bx.y, og*ti);
        __nv_bfloat16 hh = __float2bfloat16(hr);
        __nv_bfloat16 hl = __float2bfloat16(hr - __bfloat162float(hh));
        __nv_bfloat16 ih = __float2bfloat16(hi);
        __nv_bfloat16 il = __float2bfloat16(hi - __bfloat162float(ih));
        __nv_bfloat16* a2 = g_A2 + (size_t)row*KA2;
        a2[sd]=hh; a2[512+sd]=ih; a2[1024+sd]=hl; a2[1536+sd]=il;
    }
}

// ----------------------------- HMMA GEMM ---------------------------------------
// D[m][n] = sum_k A[m][k'] * W[n][k]; W is [n][KW] with KW = 3*Ks blocks
// [Whi|Wlo|Whi]; A stored deduped [Ahi|Alo] (per region), remapped per iter.
// Regions: ki < hallIters -> A2 (stride 2048, Ks=1024); else A1 (stride 1024, Ks=512).
// mode 0: n<1024 -> oBx; n>=1024 -> oGt = sigmoid(v + gb)
// mode 1: pairs (2j,2j+1)=(yr,yi): hOut = resid + 0.1*(yr*y + y)
#define ST 3
#define STAGE_BYTES 32768          // A 16KB + B 16KB
#define GEMM_SMEM (ST*STAGE_BYTES) // 96KB -> 2 CTAs/SM

__global__ void __launch_bounds__(256, 2)
mma_gemm(const __nv_bfloat16* __restrict__ A1p, const __nv_bfloat16* __restrict__ A2p,
         const __nv_bfloat16* __restrict__ W, int KW, int hallIters, int mode,
         float* __restrict__ oBx, float* __restrict__ oGt, const float* __restrict__ gb,
         const float* __restrict__ resid, float* __restrict__ hOut)
{
    extern __shared__ char smem[];
    uint32_t sb = s2u(smem);
    int tid = threadIdx.x, wid = tid >> 5, L = tid & 31;
    int m0 = blockIdx.y * 128, n0 = blockIdx.x * 128;
    const int NK = KW >> 6;

    // ---- A chunks (4 x 16B per thread per stage) ----
    uint32_t rA[4], cA[4], soffA[4];
    #pragma unroll
    for (int i = 0; i < 4; i++) {
        int q = tid + i*256;              // 0..1023
        int r = q >> 3, c = q & 7;
        rA[i] = (uint32_t)(m0 + r);
        cA[i] = (uint32_t)(c * 8);
        soffA[i] = swz((uint32_t)(r*128 + c*16));
    }
    // ---- B chunks ----
    const __nv_bfloat16* gBp[4]; uint32_t soffB[4];
    #pragma unroll
    for (int i = 0; i < 4; i++) {
        int q = (tid + (i+4)*256) & 1023;
        int r = q >> 3, c = q & 7;
        gBp[i] = W + (size_t)(n0 + r)*KW + c*8;
        soffB[i] = 16384u + swz((uint32_t)(r*128 + c*16));
    }

    // ---- ldmatrix lane addressing (SW128) ----
    int wm = wid >> 2, wn = wid & 3;
    int rowA0 = wm*64 + (L & 7) + ((L >> 3) & 1) * 8;
    uint32_t aBase = (uint32_t)rowA0 * 128; uint32_t aS = (uint32_t)(rowA0 & 7);
    uint32_t aC = (uint32_t)(L >> 4);
    int rowB0 = wn*32 + (L & 7) + ((L >> 4) & 1) * 8;
    uint32_t bBase = 16384u + (uint32_t)rowB0 * 128; uint32_t bS = (uint32_t)(rowB0 & 7);
    uint32_t bC = (uint32_t)((L >> 3) & 1);

    float c[4][4][4];
    #pragma unroll
    for (int i=0;i<4;i++)
        #pragma unroll
        for (int j=0;j<4;j++)
            #pragma unroll
            for (int e=0;e<4;e++) c[i][j][e] = 0.f;

    // stage loader
    auto load_stage = [&](int ki, uint32_t st){
        int j, nb, sh; const __nv_bfloat16* ab;
        if (ki < hallIters) { j = ki; nb = 16; sh = 11; ab = A2p; }
        else { j = ki - hallIters; nb = 8; sh = 10; ab = A1p; }
        uint32_t koff = (uint32_t)(((j < nb) ? j : j - nb) << 6);
        #pragma unroll
        for (int i = 0; i < 4; i++)
            cpa16(st + soffA[i], ab + ((rA[i] << sh) + koff + cA[i]));
        uint32_t kb = (uint32_t)(ki * 64);
        #pragma unroll
        for (int i = 0; i < 4; i++)
            cpa16(st + soffB[i], gBp[i] + kb);
    };

    // ---- prologue: load stages 0,1 ----
    #pragma unroll
    for (int s = 0; s < ST-1; s++) {
        if (s < NK) load_stage(s, sb + s*STAGE_BYTES);
        asm volatile("cp.async.commit_group;" ::: "memory");
    }

    for (int ki = 0; ki < NK; ki++) {
        asm volatile("cp.async.wait_group %0;" :: "n"(ST-2) : "memory");
        __syncthreads();

        uint32_t st = sb + (uint32_t)(ki % ST) * STAGE_BYTES;
        #pragma unroll
        for (int kk = 0; kk < 4; kk++) {
            uint32_t a[4][4], b[2][4];
            uint32_t ca = (uint32_t)(kk*2);
            #pragma unroll
            for (int mt = 0; mt < 4; mt++)
                ldsm4(a[mt], st + aBase + (uint32_t)mt*2048 + (((ca + aC) ^ aS) << 4));
            #pragma unroll
            for (int bt = 0; bt < 2; bt++)
                ldsm4(b[bt], st + bBase + (uint32_t)bt*2048 + (((ca + bC) ^ bS) << 4));
            #pragma unroll
            for (int mt = 0; mt < 4; mt++)
                #pragma unroll
                for (int nt = 0; nt < 4; nt++)
                    mma16816(c[mt][nt], a[mt], &b[nt>>1][(nt&1)*2]);
        }

        int ls = ki + ST - 1;
        if (ls < NK) load_stage(ls, sb + (uint32_t)(ls % ST) * STAGE_BYTES);
        asm volatile("cp.async.commit_group;" ::: "memory");
    }

    // ---- epilogue: direct float2 stores ----
    int lrow = L >> 2, lcol = (L & 3) * 2;
    int mRow = m0 + wm*64 + lrow;
    int nCol = n0 + wn*32 + lcol;
    #pragma unroll
    for (int mt = 0; mt < 4; mt++) {
        #pragma unroll
        for (int nt = 0; nt < 4; nt++) {
            int row = mRow + mt*16;
            int col = nCol + nt*8;
            float* cc = c[mt][nt];
            if (mode == 0) {
                if (col < 1024) {
                    float2 v0; v0.x = cc[0]; v0.y = cc[1];
                    float2 v1; v1.x = cc[2]; v1.y = cc[3];
                    *(float2*)&oBx[(size_t)row*1024 + col] = v0;
                    *(float2*)&oBx[(size_t)(row+8)*1024 + col] = v1;
                } else {
                    int gc = col - 1024;
                    float b0 = gb[gc], b1 = gb[gc+1];
                    float2 v0, v1;
                    v0.x = 1.f/(1.f+expf(-(cc[0]+b0)));
                    v0.y = 1.f/(1.f+expf(-(cc[1]+b1)));
                    v1.x = 1.f/(1.f+expf(-(cc[2]+b0)));
                    v1.y = 1.f/(1.f+expf(-(cc[3]+b1)));
                    *(float2*)&oGt[(size_t)row*512 + gc] = v0;
                    *(float2*)&oGt[(size_t)(row+8)*512 + gc] = v1;
                }
            } else {
                float2 r0 = *(const float2*)&resid[(size_t)row*512 + col];
                float2 r1 = *(const float2*)&resid[(size_t)(row+8)*512 + col];
                float2 v0, v1;
                v0.x = r0.x + 0.1f*(cc[0]*cc[0] + cc[0]);
                v0.y = r0.y + 0.1f*(cc[0]*cc[1] + cc[1]);
                v1.x = r1.x + 0.1f*(cc[2]*cc[2] + cc[2]);
                v1.y = r1.y + 0.1f*(cc[2]*cc[3] + cc[3]);
                *(float2*)&hOut[(size_t)row*512 + col] = v0;
                *(float2*)&hOut[(size_t)(row+8)*512 + col] = v1;
            }
        }
    }
}

// ----------------------------- host ---------------------------------------------
extern "C" void kernel_launch(void* const* d_in, const int* in_sizes, int n_in,
                              void* d_out, int out_size)
{
    const float* x      = (const float*)d_in[0];
    const float* h0     = (const float*)d_in[1];
    const float* theta  = (const float*)d_in[2];
    const float* damp_p = (const float*)d_in[3];
    const float* BWr    = (const float*)d_in[4];
    const float* BWi    = (const float*)d_in[5];
    const float* CWr    = (const float*)d_in[6];
    const float* CWi    = (const float*)d_in[7];
    const float* DWr    = (const float*)d_in[8];
    const float* DWi    = (const float*)d_in[9];
    const float* gW     = (const float*)d_in[10];
    const float* gb     = (const float*)d_in[11];
    const float* ng     = (const float*)d_in[12];
    const float* nb     = (const float*)d_in[13];
    const float* og     = (const float*)d_in[14];
    const float* ob     = (const float*)d_in[15];
    float* out = (float*)d_out;

    cudaFuncSetAttribute(mma_gemm, cudaFuncAttributeMaxDynamicSharedMemorySize, GEMM_SMEM);

    __nv_bfloat16 *a1, *a2, *w1, *w2;
    float *bx, *gt, *hbuf;
    cudaGetSymbolAddress((void**)&a1, g_A1);
    cudaGetSymbolAddress((void**)&a2, g_A2);
    cudaGetSymbolAddress((void**)&w1, g_W1);
    cudaGetSymbolAddress((void**)&w2, g_W2);
    cudaGetSymbolAddress((void**)&bx, g_Bx);
    cudaGetSymbolAddress((void**)&gt, g_gt);
    cudaGetSymbolAddress((void**)&hbuf, g_h);

    float* hfin = out + (size_t)Mc*Dc*2;

    {
        size_t n1 = (size_t)Lc*N1*K1;
        prep_w1<<<(unsigned)((n1+255)/256), 256>>>(BWr, BWi, gW);
        size_t n2 = (size_t)Lc*N2*K2;
        prep_w2<<<(unsigned)((n2+255)/256), 256>>>(CWr, CWi, DWr, DWi);
    }

    for (int l = 0; l < Lc; l++) {
        const float* src = (l == 0) ? x : hbuf;

        ln_kernel<<<Mc/8, 256>>>(src, ng + l*Dc, nb + l*Dc, 0, nullptr);

        // GEMM1: Bx + gates (A = A1 only; hallIters = 0)
        {
            dim3 g(N1/128, Mc/128);
            mma_gemm<<<g, 256, GEMM_SMEM>>>(a1, a1, w1 + (size_t)l*N1*K1, K1, 0, 0,
                                            bx, gt, gb + (size_t)l*SDc, nullptr, nullptr);
        }

        scan1<<<512, 256>>>(l, theta, damp_p);
        scan2<<<8, 256>>>(l, h0, hfin);
        scan3<<<512, 256>>>(l, theta, damp_p);

        // GEMM2: y = C*hall + D*xn; hall from A2 (48 iters), xn from A1
        {
            dim3 g(N2/128, Mc/128);
            mma_gemm<<<g, 256, GEMM_SMEM>>>(a1, a2, w2 + (size_t)l*N2*K2, K2, 48, 1,
                                            nullptr, nullptr, nullptr, src, hbuf);
        }
    }

    ln_kernel<<<Mc/8, 256>>>(hbuf, og, ob, 1, out);
}